// round 14
// baseline (speedup 1.0000x reference)
#include <cuda_runtime.h>
#include <cuda_bf16.h>
#include <cuda_fp16.h>
#include <cstdint>

#define B_   16
#define V_   20000
#define D_   256
#define H_   256
#define EPS_ 1e-5f

// ======================= helpers =======================
__device__ __forceinline__ uint32_t smem_u32(const void* p) {
    uint32_t a;
    asm("{ .reg .u64 t; cvta.to.shared.u64 t, %1; cvt.u32.u64 %0, t; }" : "=r"(a) : "l"(p));
    return a;
}
__device__ __forceinline__ void ldsm4(uint32_t* r, uint32_t addr) {
    asm volatile("ldmatrix.sync.aligned.m8n8.x4.shared.b16 {%0,%1,%2,%3}, [%4];"
        : "=r"(r[0]), "=r"(r[1]), "=r"(r[2]), "=r"(r[3]) : "r"(addr));
}
__device__ __forceinline__ void ldsm4t(uint32_t* r, uint32_t addr) {
    asm volatile("ldmatrix.sync.aligned.m8n8.x4.trans.shared.b16 {%0,%1,%2,%3}, [%4];"
        : "=r"(r[0]), "=r"(r[1]), "=r"(r[2]), "=r"(r[3]) : "r"(addr));
}
__device__ __forceinline__ void mma_bf16(float* c, const uint32_t* a, const uint32_t* b) {
    asm volatile("mma.sync.aligned.m16n8k16.row.col.f32.bf16.bf16.f32 "
        "{%0,%1,%2,%3}, {%4,%5,%6,%7}, {%8,%9}, {%0,%1,%2,%3};"
        : "+f"(c[0]), "+f"(c[1]), "+f"(c[2]), "+f"(c[3])
        : "r"(a[0]), "r"(a[1]), "r"(a[2]), "r"(a[3]), "r"(b[0]), "r"(b[1]));
}
__device__ __forceinline__ uint32_t pack2bf16(float a, float b) {
    unsigned short ua = __bfloat16_as_ushort(__float2bfloat16(a));
    unsigned short ub = __bfloat16_as_ushort(__float2bfloat16(b));
    return ((uint32_t)ub << 16) | ua;
}
__device__ __forceinline__ void cp16(uint32_t dst, const void* src) {
    asm volatile("cp.async.cg.shared.global [%0], [%1], 16;" :: "r"(dst), "l"(src));
}
#define CP_COMMIT() asm volatile("cp.async.commit_group;" ::: "memory")
#define CP_WAIT(n)  asm volatile("cp.async.wait_group %0;" :: "n"(n) : "memory")

// ======================= scratch =======================
__device__ float g_pht[H_ * B_];               // [h][b]
__device__ float g_scores[B_ * V_];            // [b][v]
__device__ float g_red2[256];                  // 128 blocks x (sum, sumsq)
// split weights: [mat(2)][split(2)][k(256)][n(256)] bf16
__device__ __align__(16) __nv_bfloat16 g_Bs[2 * 2 * 256 * 256];

// ---------------- prep: blocks 0..127 weight split, 128..143 patient ----------------
__global__ __launch_bounds__(1024)
void k_prep(const float* __restrict__ Wa, const float* __restrict__ W1,
            const float* __restrict__ pe, const float* __restrict__ Wp,
            const float* __restrict__ bp, const float* __restrict__ gp,
            const float* __restrict__ betap, const float* __restrict__ b1)
{
    int tid = threadIdx.x;
    if (blockIdx.x < 128) {
        int e = blockIdx.x * 1024 + tid;
        int mat = e >> 16;
        int rem = e & 65535;
        const float* W = mat ? (W1 + (size_t)D_ * H_) : Wa;
        float v = W[rem];
        __nv_bfloat16 h = __float2bfloat16(v);
        g_Bs[(size_t)(mat * 2 + 0) * 65536 + rem] = h;
        g_Bs[(size_t)(mat * 2 + 1) * 65536 + rem] = __float2bfloat16(v - __bfloat162float(h));
        return;
    }
    int b = blockIdx.x - 128;
    int d = tid & 255;
    int q = tid >> 8;
    __shared__ float s_pe[D_], s_p[D_];
    __shared__ float red[4][D_];
    __shared__ float r1[8], r2[8], bc[2];
    if (tid < 256) s_pe[tid] = pe[b * D_ + tid];
    __syncthreads();

    float part = 0.f;
    {
        const float* Wq = Wp + (size_t)(q * 64) * 256 + d;
        #pragma unroll 16
        for (int kk = 0; kk < 64; kk++)
            part = fmaf(s_pe[q * 64 + kk], Wq[(size_t)kk * 256], part);
    }
    red[q][d] = part;
    __syncthreads();

    float acc = 0.f;
    if (tid < 256) {
        acc = red[0][d] + red[1][d] + red[2][d] + red[3][d] + bp[d];
        float s1 = acc, s2 = acc * acc;
        #pragma unroll
        for (int o = 16; o; o >>= 1) {
            s1 += __shfl_xor_sync(0xffffffffu, s1, o);
            s2 += __shfl_xor_sync(0xffffffffu, s2, o);
        }
        if ((tid & 31) == 0) { r1[tid >> 5] = s1; r2[tid >> 5] = s2; }
    }
    __syncthreads();
    if (tid == 0) {
        float t1 = 0.f, t2 = 0.f;
        #pragma unroll
        for (int i = 0; i < 8; i++) { t1 += r1[i]; t2 += r2[i]; }
        float mean = t1 * (1.0f / D_);
        float var  = t2 * (1.0f / D_) - mean * mean;
        bc[0] = mean; bc[1] = rsqrtf(var + EPS_);
    }
    __syncthreads();
    if (tid < 256) s_p[d] = (acc - bc[0]) * bc[1] * gp[d] + betap[d];
    __syncthreads();

    float part2 = 0.f;
    {
        const float* W1q = W1 + (size_t)(q * 64) * 256 + d;
        #pragma unroll 16
        for (int kk = 0; kk < 64; kk++)
            part2 = fmaf(s_p[q * 64 + kk], W1q[(size_t)kk * 256], part2);
    }
    red[q][d] = part2;
    __syncthreads();
    if (tid < 256)
        g_pht[d * B_ + b] = red[0][d] + red[1][d] + red[2][d] + red[3][d] + b1[d];
}

// ---------------- fused HMMA + LN + score kernel ----------------
static constexpr uint32_t A_HI   = 0;
static constexpr uint32_t A_LO   = 32768;
static constexpr uint32_t B_B0   = 65536;
static constexpr uint32_t B_STR  = 16640;     // 16 rows x 1040B per slot
static constexpr uint32_t SMEM_SZ = 115456;   // 65536 + 3*16640
static constexpr uint32_t SO_PS = B_B0;           // dead slot 0 overlays
static constexpr uint32_t SO_PQ = B_B0 + 1024;
static constexpr uint32_t SO_MR = B_B0 + 2048;
static constexpr uint32_t S2_AH  = 0;
static constexpr uint32_t S2_PHT = 34816;
static constexpr uint32_t S2_W2  = 44032;

__global__ __launch_bounds__(256, 2)
void k_fused(const float* __restrict__ atc4,
             const float* __restrict__ ba,
             const float* __restrict__ ga,
             const float* __restrict__ betaa,
             const float* __restrict__ W2,
             const float* __restrict__ b2)
{
    extern __shared__ __align__(16) unsigned char smem[];
    uint32_t sb = smem_u32(smem);
    int tid = threadIdx.x;
    int wid = tid >> 5;
    int l   = tid & 31;
    int wm  = wid >> 2;
    int wn  = wid & 3;
    int quad = l >> 2;
    int tid4 = l & 3;
    int m0 = blockIdx.x * 64;

    auto issue = [&](int t) {
        int phase = t >> 4, c = t & 15;
        uint32_t bb = sb + B_B0 + (uint32_t)(t % 3) * B_STR;
        const __nv_bfloat16* bh = g_Bs + (size_t)(phase * 2) * 65536 + (size_t)c * 16 * 256;
        const __nv_bfloat16* bl = bh + 65536;
        #pragma unroll
        for (int it = 0; it < 2; it++) {
            int id = it * 256 + tid;
            int k = id >> 5, u = id & 31;
            uint32_t dst = bb + (uint32_t)k * 1040 + (uint32_t)u * 16;
            cp16(dst,       bh + (size_t)k * 256 + u * 8);
            cp16(dst + 512, bl + (size_t)k * 256 + u * 8);
        }
        CP_COMMIT();
    };

    issue(0);
    issue(1);

    // ---- convert atc4 tile -> bf16 hi/lo into swizzled A smem ----
    #pragma unroll
    for (int it = 0; it < 8; it++) {
        int id = it * 256 + tid;
        int row = id >> 5, u = id & 31;
        int gr = m0 + row;
        float f[8];
        if (gr < V_) {
            float4 v0 = *(const float4*)&atc4[(size_t)gr * 256 + u * 8];
            float4 v1 = *(const float4*)&atc4[(size_t)gr * 256 + u * 8 + 4];
            f[0]=v0.x; f[1]=v0.y; f[2]=v0.z; f[3]=v0.w;
            f[4]=v1.x; f[5]=v1.y; f[6]=v1.z; f[7]=v1.w;
        } else {
            #pragma unroll
            for (int i = 0; i < 8; i++) f[i] = 0.f;
        }
        float hf[8], lf[8];
        #pragma unroll
        for (int i = 0; i < 8; i++) {
            hf[i] = __bfloat162float(__float2bfloat16(f[i]));
            lf[i] = f[i] - hf[i];
        }
        uint4 hp, lp;
        hp.x = pack2bf16(hf[0], hf[1]); hp.y = pack2bf16(hf[2], hf[3]);
        hp.z = pack2bf16(hf[4], hf[5]); hp.w = pack2bf16(hf[6], hf[7]);
        lp.x = pack2bf16(lf[0], lf[1]); lp.y = pack2bf16(lf[2], lf[3]);
        lp.z = pack2bf16(lf[4], lf[5]); lp.w = pack2bf16(lf[6], lf[7]);
        uint32_t off = (uint32_t)row * 512 + (((uint32_t)u ^ ((uint32_t)row & 7)) << 4);
        *(uint4*)(smem + A_HI + off) = hp;
        *(uint4*)(smem + A_LO + off) = lp;
    }

    int ar = wm * 32 + (l & 15);
    uint32_t arx = (uint32_t)(ar & 7);
    uint32_t a_base = sb + A_HI + (uint32_t)ar * 512;
    uint32_t kusel = (uint32_t)((l >> 4) & 1);
    uint32_t b_lane = (uint32_t)(l & 15) * 1040 + (uint32_t)(wn * 64 + ((l >> 4) & 1) * 8) * 2;

    float acc[8][2][4];
    #pragma unroll
    for (int nb = 0; nb < 8; nb++)
        #pragma unroll
        for (int mb = 0; mb < 2; mb++)
            #pragma unroll
            for (int i = 0; i < 4; i++) acc[nb][mb][i] = 0.f;

    #pragma unroll 1
    for (int t = 0; t < 32; t++) {
        int c = t & 15;
        uint32_t bb = sb + B_B0 + (uint32_t)(t % 3) * B_STR;

        if (t == 31) { CP_WAIT(0); } else { CP_WAIT(1); }
        __syncthreads();           // data visible; slot (t+2)%3 consumed at t-1

        uint32_t ku = (uint32_t)(c * 2) + kusel;
        uint32_t aa = a_base + ((ku ^ arx) << 4);
        uint32_t ah0[4], ah1[4], al0[4], al1[4];
        ldsm4(ah0, aa);
        ldsm4(ah1, aa + 8192);
        ldsm4(al0, aa + 32768);
        ldsm4(al1, aa + 40960);

        uint32_t bo = bb + b_lane;
        // double-buffered B fragments: prefetch p+1 before p's mma
        uint32_t rh[2][4], rl[2][4];
        ldsm4t(rh[0], bo);
        ldsm4t(rl[0], bo + 512);
        #pragma unroll
        for (int p = 0; p < 4; p++) {
            int cur = p & 1, nxt = cur ^ 1;
            if (p < 3) {
                ldsm4t(rh[nxt], bo + (uint32_t)((p + 1) * 32));
                ldsm4t(rl[nxt], bo + (uint32_t)((p + 1) * 32) + 512);
            }
            #pragma unroll
            for (int q = 0; q < 2; q++) {
                int nb = p * 2 + q;
                mma_bf16(acc[nb][0], ah0, &rh[cur][q * 2]);
                mma_bf16(acc[nb][0], ah0, &rl[cur][q * 2]);
                mma_bf16(acc[nb][0], al0, &rh[cur][q * 2]);
                mma_bf16(acc[nb][1], ah1, &rh[cur][q * 2]);
                mma_bf16(acc[nb][1], ah1, &rl[cur][q * 2]);
                mma_bf16(acc[nb][1], al1, &rh[cur][q * 2]);
            }
        }

        if (t == 15) {
            issue(17);             // slot 2 (held chunk 14, dead since top barrier)
            __syncthreads();       // chunk-15 ldsm done -> slot 0 reusable
            float* psum = (float*)(smem + SO_PS);
            float* psq  = (float*)(smem + SO_PQ);
            float* mrs  = (float*)(smem + SO_MR);

            #pragma unroll
            for (int mb = 0; mb < 2; mb++) {
                #pragma unroll
                for (int half = 0; half < 2; half++) {
                    float s1 = 0.f, s2 = 0.f;
                    #pragma unroll
                    for (int nb = 0; nb < 8; nb++) {
                        int col = wn * 64 + nb * 8 + tid4 * 2;
                        float x0 = acc[nb][mb][half * 2 + 0] + __ldg(&ba[col]);
                        float x1 = acc[nb][mb][half * 2 + 1] + __ldg(&ba[col + 1]);
                        s1 += x0 + x1;
                        s2 = fmaf(x0, x0, fmaf(x1, x1, s2));
                    }
                    s1 += __shfl_xor_sync(0xffffffffu, s1, 1);
                    s2 += __shfl_xor_sync(0xffffffffu, s2, 1);
                    s1 += __shfl_xor_sync(0xffffffffu, s1, 2);
                    s2 += __shfl_xor_sync(0xffffffffu, s2, 2);
                    if (tid4 == 0) {
                        int row = wm * 32 + mb * 16 + quad + half * 8;
                        psum[row * 4 + wn] = s1;
                        psq[row * 4 + wn]  = s2;
                    }
                }
            }
            __syncthreads();
            if (tid < 64) {
                float s1 = psum[tid * 4] + psum[tid * 4 + 1] + psum[tid * 4 + 2] + psum[tid * 4 + 3];
                float s2 = psq[tid * 4] + psq[tid * 4 + 1] + psq[tid * 4 + 2] + psq[tid * 4 + 3];
                float mean = s1 * (1.0f / 256.0f);
                float var  = s2 * (1.0f / 256.0f) - mean * mean;
                mrs[tid * 2]     = mean;
                mrs[tid * 2 + 1] = rsqrtf(var + EPS_);
            }
            __syncthreads();
            #pragma unroll
            for (int mb = 0; mb < 2; mb++) {
                #pragma unroll
                for (int half = 0; half < 2; half++) {
                    int row = wm * 32 + mb * 16 + quad + half * 8;
                    float mean = mrs[row * 2], rstd = mrs[row * 2 + 1];
                    #pragma unroll
                    for (int nb = 0; nb < 8; nb++) {
                        int col = wn * 64 + nb * 8 + tid4 * 2;
                        float x0 = acc[nb][mb][half * 2 + 0] + __ldg(&ba[col]);
                        float x1 = acc[nb][mb][half * 2 + 1] + __ldg(&ba[col + 1]);
                        float v0 = (x0 - mean) * rstd * __ldg(&ga[col])     + __ldg(&betaa[col]);
                        float v1 = (x1 - mean) * rstd * __ldg(&ga[col + 1]) + __ldg(&betaa[col + 1]);
                        float h0 = __bfloat162float(__float2bfloat16(v0));
                        float h1 = __bfloat162float(__float2bfloat16(v1));
                        uint32_t u = (uint32_t)(col >> 3);
                        uint32_t off = (uint32_t)row * 512 + ((u ^ ((uint32_t)row & 7)) << 4)
                                     + (uint32_t)tid4 * 4;
                        *(uint32_t*)(smem + A_HI + off) = pack2bf16(h0, h1);
                        *(uint32_t*)(smem + A_LO + off) = pack2bf16(v0 - h0, v1 - h1);
                    }
                }
            }
            #pragma unroll
            for (int nb = 0; nb < 8; nb++)
                #pragma unroll
                for (int mb = 0; mb < 2; mb++)
                    #pragma unroll
                    for (int i = 0; i < 4; i++) acc[nb][mb][i] = 0.f;
            __syncthreads();       // A rewrite + stats dead before chunk 16
        } else if (t < 30) {
            issue(t + 2);
        }
    }

    // ================= score epilogue (A region is dead) =================
    #pragma unroll
    for (int mb = 0; mb < 2; mb++) {
        #pragma unroll
        for (int half = 0; half < 2; half++) {
            int row = wm * 32 + mb * 16 + quad + half * 8;
            #pragma unroll
            for (int nb = 0; nb < 8; nb++) {
                int col = wn * 64 + nb * 8 + tid4 * 2;
                __half2 h = __floats2half2_rn(acc[nb][mb][half * 2],
                                              acc[nb][mb][half * 2 + 1]);
                *(uint32_t*)(smem + S2_AH + (uint32_t)row * 516 + (uint32_t)(col >> 1) * 4)
                    = *(uint32_t*)&h;
            }
        }
    }
    {
        #pragma unroll
        for (int e = tid; e < 2048; e += 256) {
            int h = e >> 3, b2i = e & 7;
            __half2 p = __floats2half2_rn(g_pht[h * 16 + 2 * b2i], g_pht[h * 16 + 2 * b2i + 1]);
            *(uint32_t*)(smem + S2_PHT + (uint32_t)h * 36 + (uint32_t)b2i * 4) = *(uint32_t*)&p;
        }
        ((float*)(smem + S2_W2))[tid] = W2[tid];
    }
    __syncthreads();

    {
        int r  = tid >> 2;
        int bq = tid & 3;
        const float* s_w2f = (const float*)(smem + S2_W2);
        float part0 = 0.f, part1 = 0.f, part2 = 0.f, part3 = 0.f;
        uint32_t ah_base  = sb + S2_AH + (uint32_t)r * 516;
        uint32_t pht_base = sb + S2_PHT + (uint32_t)bq * 8;

        #pragma unroll 4
        for (int h2 = 0; h2 < 128; h2++) {
            uint32_t a2;
            asm("ld.shared.b32 %0, [%1];" : "=r"(a2) : "r"(ah_base + h2 * 4));
            uint32_t blo, bhi;
            asm("prmt.b32 %0, %1, %1, 0x1010;" : "=r"(blo) : "r"(a2));
            asm("prmt.b32 %0, %1, %1, 0x3232;" : "=r"(bhi) : "r"(a2));
            uint32_t p00, p01, p10, p11;
            uint32_t pa = pht_base + (uint32_t)(2 * h2) * 36;
            asm("ld.shared.b32 %0, [%1];" : "=r"(p00) : "r"(pa));
            asm("ld.shared.b32 %0, [%1];" : "=r"(p01) : "r"(pa + 4));
            asm("ld.shared.b32 %0, [%1];" : "=r"(p10) : "r"(pa + 36));
            asm("ld.shared.b32 %0, [%1];" : "=r"(p11) : "r"(pa + 40));
            uint32_t x00, x01, x10, x11;
            asm("add.rn.f16x2 %0, %1, %2;" : "=r"(x00) : "r"(blo), "r"(p00));
            asm("add.rn.f16x2 %0, %1, %2;" : "=r"(x01) : "r"(blo), "r"(p01));
            asm("add.rn.f16x2 %0, %1, %2;" : "=r"(x10) : "r"(bhi), "r"(p10));
            asm("add.rn.f16x2 %0, %1, %2;" : "=r"(x11) : "r"(bhi), "r"(p11));
            asm("tanh.approx.f16x2 %0, %1;" : "=r"(x00) : "r"(x00));
            asm("tanh.approx.f16x2 %0, %1;" : "=r"(x01) : "r"(x01));
            asm("tanh.approx.f16x2 %0, %1;" : "=r"(x10) : "r"(x10));
            asm("tanh.approx.f16x2 %0, %1;" : "=r"(x11) : "r"(x11));
            float w0 = s_w2f[2 * h2];
            float w1 = s_w2f[2 * h2 + 1];
            float2 f00 = __half22float2(*(__half2*)&x00);
            float2 f01 = __half22float2(*(__half2*)&x01);
            float2 f10 = __half22float2(*(__half2*)&x10);
            float2 f11 = __half22float2(*(__half2*)&x11);
            part0 = fmaf(w0, f00.x, part0); part0 = fmaf(w1, f10.x, part0);
            part1 = fmaf(w0, f00.y, part1); part1 = fmaf(w1, f10.y, part1);
            part2 = fmaf(w0, f01.x, part2); part2 = fmaf(w1, f11.x, part2);
            part3 = fmaf(w0, f01.y, part3); part3 = fmaf(w1, f11.y, part3);
        }
        int grow = m0 + r;
        if (grow < V_) {
            float b2v = b2[0];
            g_scores[(size_t)(4 * bq + 0) * V_ + grow] = part0 + b2v;
            g_scores[(size_t)(4 * bq + 1) * V_ + grow] = part1 + b2v;
            g_scores[(size_t)(4 * bq + 2) * V_ + grow] = part2 + b2v;
            g_scores[(size_t)(4 * bq + 3) * V_ + grow] = part3 + b2v;
        }
    }
}

// ---------------- LN over V, stage 1: partial sums (128 blocks) ----------------
__global__ __launch_bounds__(256)
void k_red()
{
    int bx = blockIdx.x;            // 0..127
    int b = bx >> 3, s = bx & 7;
    const float4* row = (const float4*)&g_scores[(size_t)b * V_];
    int base = s * 625;
    float s1 = 0.f, s2 = 0.f;
    for (int i = threadIdx.x; i < 625; i += 256) {
        float4 x = row[base + i];
        s1 += x.x + x.y + x.z + x.w;
        s2 = fmaf(x.x, x.x, fmaf(x.y, x.y, fmaf(x.z, x.z, fmaf(x.w, x.w, s2))));
    }
    #pragma unroll
    for (int o = 16; o; o >>= 1) {
        s1 += __shfl_xor_sync(0xffffffffu, s1, o);
        s2 += __shfl_xor_sync(0xffffffffu, s2, o);
    }
    __shared__ float r1[8], r2[8];
    int w = threadIdx.x >> 5, ll = threadIdx.x & 31;
    if (ll == 0) { r1[w] = s1; r2[w] = s2; }
    __syncthreads();
    if (threadIdx.x == 0) {
        float t1 = 0.f, t2 = 0.f;
        #pragma unroll
        for (int i = 0; i < 8; i++) { t1 += r1[i]; t2 += r2[i]; }
        g_red2[bx * 2]     = t1;
        g_red2[bx * 2 + 1] = t2;
    }
}

// ---------------- LN over V, stage 2: normalize (640 blocks) ----------------
__global__ __launch_bounds__(256)
void k_norm(const float* __restrict__ g_pred,
            const float* __restrict__ b_pred,
            float* __restrict__ out)
{
    int bx = blockIdx.x;            // 0..639
    int b = bx / 40, s = bx % 40;
    float t1 = 0.f, t2 = 0.f;
    #pragma unroll
    for (int i = 0; i < 8; i++) {
        t1 += g_red2[(b * 8 + i) * 2];
        t2 += g_red2[(b * 8 + i) * 2 + 1];
    }
    float mean = t1 * (1.0f / V_);
    float var  = t2 * (1.0f / V_) - mean * mean;
    float rstd = rsqrtf(var + EPS_);

    const float4* row = (const float4*)&g_scores[(size_t)b * V_];
    const float4* gp4 = (const float4*)g_pred;
    const float4* bp4 = (const float4*)b_pred;
    float4* out4 = (float4*)&out[(size_t)b * V_];
    int base = s * 125;             // 40 * 125 = 5000 = V/4
    for (int i = threadIdx.x; i < 125; i += 256) {
        float4 x = row[base + i];
        float4 g = gp4[base + i];
        float4 be = bp4[base + i];
        float4 o;
        o.x = (x.x - mean) * rstd * g.x + be.x;
        o.y = (x.y - mean) * rstd * g.y + be.y;
        o.z = (x.z - mean) * rstd * g.z + be.z;
        o.w = (x.w - mean) * rstd * g.w + be.w;
        out4[base + i] = o;
    }
}

// ---------------- launch ----------------
extern "C" void kernel_launch(void* const* d_in, const int* in_sizes, int n_in,
                              void* d_out, int out_size)
{
    const float* pe     = (const float*)d_in[0];
    const float* atc4   = (const float*)d_in[1];
    const float* Wp     = (const float*)d_in[2];
    const float* bp     = (const float*)d_in[3];
    const float* gp     = (const float*)d_in[4];
    const float* betap  = (const float*)d_in[5];
    const float* Wa     = (const float*)d_in[6];
    const float* ba     = (const float*)d_in[7];
    const float* ga     = (const float*)d_in[8];
    const float* betaa  = (const float*)d_in[9];
    const float* W1     = (const float*)d_in[10];
    const float* b1     = (const float*)d_in[11];
    const float* W2     = (const float*)d_in[12];
    const float* b2     = (const float*)d_in[13];
    const float* gpred  = (const float*)d_in[14];
    const float* bpred  = (const float*)d_in[15];
    float* out = (float*)d_out;
    (void)in_sizes; (void)n_in; (void)out_size;

    cudaFuncSetAttribute(k_fused, cudaFuncAttributeMaxDynamicSharedMemorySize, SMEM_SZ);

    k_prep<<<144, 1024>>>(Wa, W1, pe, Wp, bp, gp, betap, b1);

    int tiles = (V_ + 63) / 64;   // 313
    k_fused<<<tiles, 256, SMEM_SZ>>>(atc4, ba, ga, betaa, W2, b2);

    k_red<<<128, 256>>>();
    k_norm<<<640, 256>>>(gpred, bpred, out);
}

// round 15
// speedup vs baseline: 1.0333x; 1.0333x over previous
#include <cuda_runtime.h>
#include <cuda_bf16.h>
#include <cuda_fp16.h>
#include <cstdint>

#define B_   16
#define V_   20000
#define D_   256
#define H_   256
#define EPS_ 1e-5f

// ======================= helpers =======================
__device__ __forceinline__ uint32_t smem_u32(const void* p) {
    uint32_t a;
    asm("{ .reg .u64 t; cvta.to.shared.u64 t, %1; cvt.u32.u64 %0, t; }" : "=r"(a) : "l"(p));
    return a;
}
__device__ __forceinline__ void ldsm4(uint32_t* r, uint32_t addr) {
    asm volatile("ldmatrix.sync.aligned.m8n8.x4.shared.b16 {%0,%1,%2,%3}, [%4];"
        : "=r"(r[0]), "=r"(r[1]), "=r"(r[2]), "=r"(r[3]) : "r"(addr));
}
__device__ __forceinline__ void ldsm4t(uint32_t* r, uint32_t addr) {
    asm volatile("ldmatrix.sync.aligned.m8n8.x4.trans.shared.b16 {%0,%1,%2,%3}, [%4];"
        : "=r"(r[0]), "=r"(r[1]), "=r"(r[2]), "=r"(r[3]) : "r"(addr));
}
__device__ __forceinline__ void mma_bf16(float* c, const uint32_t* a, const uint32_t* b) {
    asm volatile("mma.sync.aligned.m16n8k16.row.col.f32.bf16.bf16.f32 "
        "{%0,%1,%2,%3}, {%4,%5,%6,%7}, {%8,%9}, {%0,%1,%2,%3};"
        : "+f"(c[0]), "+f"(c[1]), "+f"(c[2]), "+f"(c[3])
        : "r"(a[0]), "r"(a[1]), "r"(a[2]), "r"(a[3]), "r"(b[0]), "r"(b[1]));
}
__device__ __forceinline__ uint32_t pack2bf16(float a, float b) {
    unsigned short ua = __bfloat16_as_ushort(__float2bfloat16(a));
    unsigned short ub = __bfloat16_as_ushort(__float2bfloat16(b));
    return ((uint32_t)ub << 16) | ua;
}
__device__ __forceinline__ void cp16(uint32_t dst, const void* src) {
    asm volatile("cp.async.cg.shared.global [%0], [%1], 16;" :: "r"(dst), "l"(src));
}
#define CP_COMMIT() asm volatile("cp.async.commit_group;" ::: "memory")
#define CP_WAIT(n)  asm volatile("cp.async.wait_group %0;" :: "n"(n) : "memory")

// ======================= scratch =======================
__device__ float g_pht[H_ * B_];               // [h][b]
__device__ float g_scores[B_ * V_];            // [b][v]
__device__ float g_red2[256];                  // 128 blocks x (sum, sumsq)
// split weights: [mat(2)][split(2)][k(256)][n(256)] bf16
__device__ __align__(16) __nv_bfloat16 g_Bs[2 * 2 * 256 * 256];

// ---------------- prep: blocks 0..127 weight split, 128..143 patient ----------------
__global__ __launch_bounds__(1024)
void k_prep(const float* __restrict__ Wa, const float* __restrict__ W1,
            const float* __restrict__ pe, const float* __restrict__ Wp,
            const float* __restrict__ bp, const float* __restrict__ gp,
            const float* __restrict__ betap, const float* __restrict__ b1)
{
    int tid = threadIdx.x;
    if (blockIdx.x < 128) {
        int e = blockIdx.x * 1024 + tid;
        int mat = e >> 16;
        int rem = e & 65535;
        const float* W = mat ? (W1 + (size_t)D_ * H_) : Wa;
        float v = W[rem];
        __nv_bfloat16 h = __float2bfloat16(v);
        g_Bs[(size_t)(mat * 2 + 0) * 65536 + rem] = h;
        g_Bs[(size_t)(mat * 2 + 1) * 65536 + rem] = __float2bfloat16(v - __bfloat162float(h));
        return;
    }
    int b = blockIdx.x - 128;
    int d = tid & 255;
    int q = tid >> 8;
    __shared__ float s_pe[D_], s_p[D_];
    __shared__ float red[4][D_];
    __shared__ float r1[8], r2[8], bc[2];
    if (tid < 256) s_pe[tid] = pe[b * D_ + tid];
    __syncthreads();

    float part = 0.f;
    {
        const float* Wq = Wp + (size_t)(q * 64) * 256 + d;
        #pragma unroll 16
        for (int kk = 0; kk < 64; kk++)
            part = fmaf(s_pe[q * 64 + kk], Wq[(size_t)kk * 256], part);
    }
    red[q][d] = part;
    __syncthreads();

    float acc = 0.f;
    if (tid < 256) {
        acc = red[0][d] + red[1][d] + red[2][d] + red[3][d] + bp[d];
        float s1 = acc, s2 = acc * acc;
        #pragma unroll
        for (int o = 16; o; o >>= 1) {
            s1 += __shfl_xor_sync(0xffffffffu, s1, o);
            s2 += __shfl_xor_sync(0xffffffffu, s2, o);
        }
        if ((tid & 31) == 0) { r1[tid >> 5] = s1; r2[tid >> 5] = s2; }
    }
    __syncthreads();
    if (tid == 0) {
        float t1 = 0.f, t2 = 0.f;
        #pragma unroll
        for (int i = 0; i < 8; i++) { t1 += r1[i]; t2 += r2[i]; }
        float mean = t1 * (1.0f / D_);
        float var  = t2 * (1.0f / D_) - mean * mean;
        bc[0] = mean; bc[1] = rsqrtf(var + EPS_);
    }
    __syncthreads();
    if (tid < 256) s_p[d] = (acc - bc[0]) * bc[1] * gp[d] + betap[d];
    __syncthreads();

    float part2 = 0.f;
    {
        const float* W1q = W1 + (size_t)(q * 64) * 256 + d;
        #pragma unroll 16
        for (int kk = 0; kk < 64; kk++)
            part2 = fmaf(s_p[q * 64 + kk], W1q[(size_t)kk * 256], part2);
    }
    red[q][d] = part2;
    __syncthreads();
    if (tid < 256)
        g_pht[d * B_ + b] = red[0][d] + red[1][d] + red[2][d] + red[3][d] + b1[d];
}

// ---------------- fused HMMA + LN + score kernel ----------------
static constexpr uint32_t A_HI   = 0;
static constexpr uint32_t A_LO   = 32768;
static constexpr uint32_t B_B0   = 65536;
static constexpr uint32_t B_STR  = 16640;     // 16 rows x 1040B per slot
static constexpr uint32_t SMEM_SZ = 115456;   // 65536 + 3*16640
static constexpr uint32_t SO_PS = B_B0;           // dead slot 0 overlays
static constexpr uint32_t SO_PQ = B_B0 + 1024;
static constexpr uint32_t SO_MR = B_B0 + 2048;
static constexpr uint32_t S2_AH  = 0;
static constexpr uint32_t S2_PHT = 34816;
static constexpr uint32_t S2_W2  = 44032;

__global__ __launch_bounds__(256, 2)
void k_fused(const float* __restrict__ atc4,
             const float* __restrict__ ba,
             const float* __restrict__ ga,
             const float* __restrict__ betaa,
             const float* __restrict__ W2,
             const float* __restrict__ b2)
{
    extern __shared__ __align__(16) unsigned char smem[];
    uint32_t sb = smem_u32(smem);
    int tid = threadIdx.x;
    int wid = tid >> 5;
    int l   = tid & 31;
    int wm  = wid >> 2;
    int wn  = wid & 3;
    int quad = l >> 2;
    int tid4 = l & 3;
    int m0 = blockIdx.x * 64;

    auto issue = [&](int t) {
        int phase = t >> 4, c = t & 15;
        uint32_t bb = sb + B_B0 + (uint32_t)(t % 3) * B_STR;
        const __nv_bfloat16* bh = g_Bs + (size_t)(phase * 2) * 65536 + (size_t)c * 16 * 256;
        const __nv_bfloat16* bl = bh + 65536;
        #pragma unroll
        for (int it = 0; it < 2; it++) {
            int id = it * 256 + tid;       // 0..511
            int k = id >> 5, u = id & 31;
            uint32_t dst = bb + (uint32_t)k * 1040 + (uint32_t)u * 16;
            cp16(dst,       bh + (size_t)k * 256 + u * 8);
            cp16(dst + 512, bl + (size_t)k * 256 + u * 8);
        }
        CP_COMMIT();
    };

    issue(0);
    issue(1);

    // ---- convert atc4 tile -> bf16 hi/lo into swizzled A smem ----
    #pragma unroll
    for (int it = 0; it < 8; it++) {
        int id = it * 256 + tid;
        int row = id >> 5, u = id & 31;
        int gr = m0 + row;
        float f[8];
        if (gr < V_) {
            float4 v0 = *(const float4*)&atc4[(size_t)gr * 256 + u * 8];
            float4 v1 = *(const float4*)&atc4[(size_t)gr * 256 + u * 8 + 4];
            f[0]=v0.x; f[1]=v0.y; f[2]=v0.z; f[3]=v0.w;
            f[4]=v1.x; f[5]=v1.y; f[6]=v1.z; f[7]=v1.w;
        } else {
            #pragma unroll
            for (int i = 0; i < 8; i++) f[i] = 0.f;
        }
        float hf[8], lf[8];
        #pragma unroll
        for (int i = 0; i < 8; i++) {
            hf[i] = __bfloat162float(__float2bfloat16(f[i]));
            lf[i] = f[i] - hf[i];
        }
        uint4 hp, lp;
        hp.x = pack2bf16(hf[0], hf[1]); hp.y = pack2bf16(hf[2], hf[3]);
        hp.z = pack2bf16(hf[4], hf[5]); hp.w = pack2bf16(hf[6], hf[7]);
        lp.x = pack2bf16(lf[0], lf[1]); lp.y = pack2bf16(lf[2], lf[3]);
        lp.z = pack2bf16(lf[4], lf[5]); lp.w = pack2bf16(lf[6], lf[7]);
        uint32_t off = (uint32_t)row * 512 + (((uint32_t)u ^ ((uint32_t)row & 7)) << 4);
        *(uint4*)(smem + A_HI + off) = hp;
        *(uint4*)(smem + A_LO + off) = lp;
    }

    int ar = wm * 32 + (l & 15);
    uint32_t arx = (uint32_t)(ar & 7);
    uint32_t a_base = sb + A_HI + (uint32_t)ar * 512;
    uint32_t kusel = (uint32_t)((l >> 4) & 1);
    uint32_t b_lane = (uint32_t)(l & 15) * 1040 + (uint32_t)(wn * 64 + ((l >> 4) & 1) * 8) * 2;

    float acc[8][2][4];
    #pragma unroll
    for (int nb = 0; nb < 8; nb++)
        #pragma unroll
        for (int mb = 0; mb < 2; mb++)
            #pragma unroll
            for (int i = 0; i < 4; i++) acc[nb][mb][i] = 0.f;

    #pragma unroll 1
    for (int t = 0; t < 32; t++) {
        int c = t & 15;
        uint32_t bb = sb + B_B0 + (uint32_t)(t % 3) * B_STR;

        if (t == 31) { CP_WAIT(0); } else { CP_WAIT(1); }
        __syncthreads();           // data visible; slot (t+2)%3 consumed at t-1

        uint32_t ku = (uint32_t)(c * 2) + kusel;
        uint32_t aa = a_base + ((ku ^ arx) << 4);
        uint32_t ah0[4], ah1[4], al0[4], al1[4];
        ldsm4(ah0, aa);
        ldsm4(ah1, aa + 8192);
        ldsm4(al0, aa + 32768);
        ldsm4(al1, aa + 40960);
        #pragma unroll
        for (int p = 0; p < 4; p++) {
            uint32_t bo = bb + b_lane + (uint32_t)(p * 32);
            uint32_t rh[4], rl[4];
            ldsm4t(rh, bo);
            ldsm4t(rl, bo + 512);
            #pragma unroll
            for (int q = 0; q < 2; q++) {
                int nb = p * 2 + q;
                mma_bf16(acc[nb][0], ah0, &rh[q * 2]);
                mma_bf16(acc[nb][0], ah0, &rl[q * 2]);
                mma_bf16(acc[nb][0], al0, &rh[q * 2]);
                mma_bf16(acc[nb][1], ah1, &rh[q * 2]);
                mma_bf16(acc[nb][1], ah1, &rl[q * 2]);
                mma_bf16(acc[nb][1], al1, &rh[q * 2]);
            }
        }

        if (t == 15) {
            issue(17);             // slot 2 (held chunk 14, dead since top barrier)
            __syncthreads();       // chunk-15 ldsm done -> slot 0 reusable
            float* psum = (float*)(smem + SO_PS);
            float* psq  = (float*)(smem + SO_PQ);
            float* mrs  = (float*)(smem + SO_MR);

            #pragma unroll
            for (int mb = 0; mb < 2; mb++) {
                #pragma unroll
                for (int half = 0; half < 2; half++) {
                    float s1 = 0.f, s2 = 0.f;
                    #pragma unroll
                    for (int nb = 0; nb < 8; nb++) {
                        int col = wn * 64 + nb * 8 + tid4 * 2;
                        float x0 = acc[nb][mb][half * 2 + 0] + __ldg(&ba[col]);
                        float x1 = acc[nb][mb][half * 2 + 1] + __ldg(&ba[col + 1]);
                        s1 += x0 + x1;
                        s2 = fmaf(x0, x0, fmaf(x1, x1, s2));
                    }
                    s1 += __shfl_xor_sync(0xffffffffu, s1, 1);
                    s2 += __shfl_xor_sync(0xffffffffu, s2, 1);
                    s1 += __shfl_xor_sync(0xffffffffu, s1, 2);
                    s2 += __shfl_xor_sync(0xffffffffu, s2, 2);
                    if (tid4 == 0) {
                        int row = wm * 32 + mb * 16 + quad + half * 8;
                        psum[row * 4 + wn] = s1;
                        psq[row * 4 + wn]  = s2;
                    }
                }
            }
            __syncthreads();
            if (tid < 64) {
                float s1 = psum[tid * 4] + psum[tid * 4 + 1] + psum[tid * 4 + 2] + psum[tid * 4 + 3];
                float s2 = psq[tid * 4] + psq[tid * 4 + 1] + psq[tid * 4 + 2] + psq[tid * 4 + 3];
                float mean = s1 * (1.0f / 256.0f);
                float var  = s2 * (1.0f / 256.0f) - mean * mean;
                mrs[tid * 2]     = mean;
                mrs[tid * 2 + 1] = rsqrtf(var + EPS_);
            }
            __syncthreads();
            #pragma unroll
            for (int mb = 0; mb < 2; mb++) {
                #pragma unroll
                for (int half = 0; half < 2; half++) {
                    int row = wm * 32 + mb * 16 + quad + half * 8;
                    float mean = mrs[row * 2], rstd = mrs[row * 2 + 1];
                    #pragma unroll
                    for (int nb = 0; nb < 8; nb++) {
                        int col = wn * 64 + nb * 8 + tid4 * 2;
                        float x0 = acc[nb][mb][half * 2 + 0] + __ldg(&ba[col]);
                        float x1 = acc[nb][mb][half * 2 + 1] + __ldg(&ba[col + 1]);
                        float v0 = (x0 - mean) * rstd * __ldg(&ga[col])     + __ldg(&betaa[col]);
                        float v1 = (x1 - mean) * rstd * __ldg(&ga[col + 1]) + __ldg(&betaa[col + 1]);
                        float h0 = __bfloat162float(__float2bfloat16(v0));
                        float h1 = __bfloat162float(__float2bfloat16(v1));
                        uint32_t u = (uint32_t)(col >> 3);
                        uint32_t off = (uint32_t)row * 512 + ((u ^ ((uint32_t)row & 7)) << 4)
                                     + (uint32_t)tid4 * 4;
                        *(uint32_t*)(smem + A_HI + off) = pack2bf16(h0, h1);
                        *(uint32_t*)(smem + A_LO + off) = pack2bf16(v0 - h0, v1 - h1);
                    }
                }
            }
            #pragma unroll
            for (int nb = 0; nb < 8; nb++)
                #pragma unroll
                for (int mb = 0; mb < 2; mb++)
                    #pragma unroll
                    for (int i = 0; i < 4; i++) acc[nb][mb][i] = 0.f;
            __syncthreads();       // A rewrite + stats dead before chunk 16
        } else if (t < 30) {
            issue(t + 2);
        }
    }

    // ================= score epilogue (A region is dead) =================
    #pragma unroll
    for (int mb = 0; mb < 2; mb++) {
        #pragma unroll
        for (int half = 0; half < 2; half++) {
            int row = wm * 32 + mb * 16 + quad + half * 8;
            #pragma unroll
            for (int nb = 0; nb < 8; nb++) {
                int col = wn * 64 + nb * 8 + tid4 * 2;
                __half2 h = __floats2half2_rn(acc[nb][mb][half * 2],
                                              acc[nb][mb][half * 2 + 1]);
                *(uint32_t*)(smem + S2_AH + (uint32_t)row * 516 + (uint32_t)(col >> 1) * 4)
                    = *(uint32_t*)&h;
            }
        }
    }
    {
        #pragma unroll
        for (int e = tid; e < 2048; e += 256) {
            int h = e >> 3, b2i = e & 7;
            __half2 p = __floats2half2_rn(g_pht[h * 16 + 2 * b2i], g_pht[h * 16 + 2 * b2i + 1]);
            *(uint32_t*)(smem + S2_PHT + (uint32_t)h * 36 + (uint32_t)b2i * 4) = *(uint32_t*)&p;
        }
        ((float*)(smem + S2_W2))[tid] = W2[tid];
    }
    __syncthreads();

    {
        int r  = tid >> 2;
        int bq = tid & 3;
        const float* s_w2f = (const float*)(smem + S2_W2);
        float part0 = 0.f, part1 = 0.f, part2 = 0.f, part3 = 0.f;
        uint32_t ah_base  = sb + S2_AH + (uint32_t)r * 516;
        uint32_t pht_base = sb + S2_PHT + (uint32_t)bq * 8;

        #pragma unroll 4
        for (int h2 = 0; h2 < 128; h2++) {
            uint32_t a2;
            asm("ld.shared.b32 %0, [%1];" : "=r"(a2) : "r"(ah_base + h2 * 4));
            uint32_t blo, bhi;
            asm("prmt.b32 %0, %1, %1, 0x1010;" : "=r"(blo) : "r"(a2));
            asm("prmt.b32 %0, %1, %1, 0x3232;" : "=r"(bhi) : "r"(a2));
            uint32_t p00, p01, p10, p11;
            uint32_t pa = pht_base + (uint32_t)(2 * h2) * 36;
            asm("ld.shared.b32 %0, [%1];" : "=r"(p00) : "r"(pa));
            asm("ld.shared.b32 %0, [%1];" : "=r"(p01) : "r"(pa + 4));
            asm("ld.shared.b32 %0, [%1];" : "=r"(p10) : "r"(pa + 36));
            asm("ld.shared.b32 %0, [%1];" : "=r"(p11) : "r"(pa + 40));
            uint32_t x00, x01, x10, x11;
            asm("add.rn.f16x2 %0, %1, %2;" : "=r"(x00) : "r"(blo), "r"(p00));
            asm("add.rn.f16x2 %0, %1, %2;" : "=r"(x01) : "r"(blo), "r"(p01));
            asm("add.rn.f16x2 %0, %1, %2;" : "=r"(x10) : "r"(bhi), "r"(p10));
            asm("add.rn.f16x2 %0, %1, %2;" : "=r"(x11) : "r"(bhi), "r"(p11));
            asm("tanh.approx.f16x2 %0, %1;" : "=r"(x00) : "r"(x00));
            asm("tanh.approx.f16x2 %0, %1;" : "=r"(x01) : "r"(x01));
            asm("tanh.approx.f16x2 %0, %1;" : "=r"(x10) : "r"(x10));
            asm("tanh.approx.f16x2 %0, %1;" : "=r"(x11) : "r"(x11));
            float w0 = s_w2f[2 * h2];
            float w1 = s_w2f[2 * h2 + 1];
            float2 f00 = __half22float2(*(__half2*)&x00);
            float2 f01 = __half22float2(*(__half2*)&x01);
            float2 f10 = __half22float2(*(__half2*)&x10);
            float2 f11 = __half22float2(*(__half2*)&x11);
            part0 = fmaf(w0, f00.x, part0); part0 = fmaf(w1, f10.x, part0);
            part1 = fmaf(w0, f00.y, part1); part1 = fmaf(w1, f10.y, part1);
            part2 = fmaf(w0, f01.x, part2); part2 = fmaf(w1, f11.x, part2);
            part3 = fmaf(w0, f01.y, part3); part3 = fmaf(w1, f11.y, part3);
        }
        int grow = m0 + r;
        if (grow < V_) {
            float b2v = b2[0];
            g_scores[(size_t)(4 * bq + 0) * V_ + grow] = part0 + b2v;
            g_scores[(size_t)(4 * bq + 1) * V_ + grow] = part1 + b2v;
            g_scores[(size_t)(4 * bq + 2) * V_ + grow] = part2 + b2v;
            g_scores[(size_t)(4 * bq + 3) * V_ + grow] = part3 + b2v;
        }
    }
}

// ---------------- LN over V, stage 1: partial sums (128 blocks) ----------------
__global__ __launch_bounds__(256)
void k_red()
{
    int bx = blockIdx.x;            // 0..127
    int b = bx >> 3, s = bx & 7;
    const float4* row = (const float4*)&g_scores[(size_t)b * V_];
    int base = s * 625;
    float s1 = 0.f, s2 = 0.f;
    for (int i = threadIdx.x; i < 625; i += 256) {
        float4 x = row[base + i];
        s1 += x.x + x.y + x.z + x.w;
        s2 = fmaf(x.x, x.x, fmaf(x.y, x.y, fmaf(x.z, x.z, fmaf(x.w, x.w, s2))));
    }
    #pragma unroll
    for (int o = 16; o; o >>= 1) {
        s1 += __shfl_xor_sync(0xffffffffu, s1, o);
        s2 += __shfl_xor_sync(0xffffffffu, s2, o);
    }
    __shared__ float r1[8], r2[8];
    int w = threadIdx.x >> 5, ll = threadIdx.x & 31;
    if (ll == 0) { r1[w] = s1; r2[w] = s2; }
    __syncthreads();
    if (threadIdx.x == 0) {
        float t1 = 0.f, t2 = 0.f;
        #pragma unroll
        for (int i = 0; i < 8; i++) { t1 += r1[i]; t2 += r2[i]; }
        g_red2[bx * 2]     = t1;
        g_red2[bx * 2 + 1] = t2;
    }
}

// ---------------- LN over V, stage 2: normalize (640 blocks) ----------------
__global__ __launch_bounds__(256)
void k_norm(const float* __restrict__ g_pred,
            const float* __restrict__ b_pred,
            float* __restrict__ out)
{
    int bx = blockIdx.x;            // 0..639
    int b = bx / 40, s = bx % 40;
    float t1 = 0.f, t2 = 0.f;
    #pragma unroll
    for (int i = 0; i < 8; i++) {
        t1 += g_red2[(b * 8 + i) * 2];
        t2 += g_red2[(b * 8 + i) * 2 + 1];
    }
    float mean = t1 * (1.0f / V_);
    float var  = t2 * (1.0f / V_) - mean * mean;
    float rstd = rsqrtf(var + EPS_);

    const float4* row = (const float4*)&g_scores[(size_t)b * V_];
    const float4* gp4 = (const float4*)g_pred;
    const float4* bp4 = (const float4*)b_pred;
    float4* out4 = (float4*)&out[(size_t)b * V_];
    int base = s * 125;             // 40 * 125 = 5000 = V/4
    for (int i = threadIdx.x; i < 125; i += 256) {
        float4 x = row[base + i];
        float4 g = gp4[base + i];
        float4 be = bp4[base + i];
        float4 o;
        o.x = (x.x - mean) * rstd * g.x + be.x;
        o.y = (x.y - mean) * rstd * g.y + be.y;
        o.z = (x.z - mean) * rstd * g.z + be.z;
        o.w = (x.w - mean) * rstd * g.w + be.w;
        out4[base + i] = o;
    }
}

// ---------------- launch ----------------
extern "C" void kernel_launch(void* const* d_in, const int* in_sizes, int n_in,
                              void* d_out, int out_size)
{
    const float* pe     = (const float*)d_in[0];
    const float* atc4   = (const float*)d_in[1];
    const float* Wp     = (const float*)d_in[2];
    const float* bp     = (const float*)d_in[3];
    const float* gp     = (const float*)d_in[4];
    const float* betap  = (const float*)d_in[5];
    const float* Wa     = (const float*)d_in[6];
    const float* ba     = (const float*)d_in[7];
    const float* ga     = (const float*)d_in[8];
    const float* betaa  = (const float*)d_in[9];
    const float* W1     = (const float*)d_in[10];
    const float* b1     = (const float*)d_in[11];
    const float* W2     = (const float*)d_in[12];
    const float* b2     = (const float*)d_in[13];
    const float* gpred  = (const float*)d_in[14];
    const float* bpred  = (const float*)d_in[15];
    float* out = (float*)d_out;
    (void)in_sizes; (void)n_in; (void)out_size;

    cudaFuncSetAttribute(k_fused, cudaFuncAttributeMaxDynamicSharedMemorySize, SMEM_SZ);

    k_prep<<<144, 1024>>>(Wa, W1, pe, Wp, bp, gp, betap, b1);

    int tiles = (V_ + 63) / 64;   // 313
    k_fused<<<tiles, 256, SMEM_SZ>>>(atc4, ba, ga, betaa, W2, b2);

    k_red<<<128, 256>>>();
    k_norm<<<640, 256>>>(gpred, bpred, out);
}